// round 2
// baseline (speedup 1.0000x reference)
#include <cuda_runtime.h>
#include <cub/cub.cuh>
#include <math.h>

// ---------------------------------------------------------------------------
// Problem: loss = sum_i event_i*(log(denom_i) - xbeta0_i) + n*lv0
//               + clip(exp(-lv1),0,1) * cost2 + lv1
// where order = stable descending sort by time, denom = cumsum(exp(xbeta0[order])),
// cost2 = M(M+1)/2 - sum_ii exp(-xh_ii) * cumsum(exp(xh))[ii],  xh = xbeta1[order][Hj]
// ---------------------------------------------------------------------------

#define MAXN (1 << 19)
#define MAXM 16384
#define T1 256
#define EPT 8
#define PER_BLOCK (T1 * EPT)          // 2048 elements per block
#define MAXB (MAXN / PER_BLOCK)       // 256
#define MAXTT (MAXB * T1)             // 65536

// scratch (allocation-free: __device__ globals)
__device__ unsigned long long g_keys_in[MAXN];
__device__ unsigned long long g_keys_out[MAXN];
__device__ unsigned char      g_cub_temp[32u << 20];
__device__ float2             g_sx[MAXN];        // (xbeta0, event) in sorted order
__device__ double             g_threadSums[MAXTT];
__device__ double             g_threadOffs[MAXTT];
__device__ double             g_blockAcc[MAXB];
__device__ float              g_xh[MAXM];
__device__ double             g_cost2;

// --- build sortable keys: flipped float bits (monotone) + tie-break index ---
__global__ void build_keys(const float* __restrict__ yt0, int n, int idx_bits,
                           unsigned idx_mask) {
    int i = blockIdx.x * blockDim.x + threadIdx.x;
    if (i >= n) return;
    unsigned u = __float_as_uint(yt0[2 * i]);            // time at [i,0]
    u = (u & 0x80000000u) ? ~u : (u | 0x80000000u);      // total order
    g_keys_in[i] = ((unsigned long long)u << idx_bits) |
                   (unsigned long long)(idx_mask - (unsigned)i); // ties: lower i first (desc sort)
}

// --- phase 1: gather (xbeta, event) in sorted order; per-thread exp-sums ---
__global__ void phase1(const float* __restrict__ yt0, const float* __restrict__ yp0,
                       int n, unsigned idx_mask) {
    int gid = blockIdx.x * blockDim.x + threadIdx.x;
    long base = (long)gid * EPT;
    double s = 0.0;
#pragma unroll
    for (int e = 0; e < EPT; e++) {
        long i = base + e;
        if (i < n) {
            unsigned long long k = g_keys_out[i];
            unsigned orig = idx_mask - (unsigned)(k & idx_mask);
            float xb = yp0[orig];
            float ev = yt0[2 * orig + 1];
            g_sx[i] = make_float2(xb, ev);
            s += (double)expf(xb);
        }
    }
    g_threadSums[gid] = s;
}

// --- phase 2: single-block exclusive scan over all per-thread sums ---
__global__ void phase2(int TT) {
    int t = threadIdx.x;
    int S = (TT + 1023) / 1024;
    long b0 = (long)t * S;
    double tot = 0.0;
    for (int k = 0; k < S; k++) {
        long i = b0 + k;
        if (i < TT) tot += g_threadSums[i];
    }
    __shared__ double sh[1024];
    sh[t] = tot;
    __syncthreads();
    for (int off = 1; off < 1024; off <<= 1) {
        double v = (t >= off) ? sh[t - off] : 0.0;
        __syncthreads();
        sh[t] += v;
        __syncthreads();
    }
    double run = sh[t] - tot;   // exclusive prefix for this thread's segment
    for (int k = 0; k < S; k++) {
        long i = b0 + k;
        if (i < TT) {
            double s = g_threadSums[i];
            g_threadOffs[i] = run;
            run += s;
        }
    }
}

// --- phase 3: per-element running denom + event-gated loss accumulation ---
__global__ void phase3(int n) {
    int gid = blockIdx.x * blockDim.x + threadIdx.x;
    long base = (long)gid * EPT;
    double run = g_threadOffs[gid];
    double acc = 0.0;
#pragma unroll
    for (int e = 0; e < EPT; e++) {
        long i = base + e;
        if (i < n) {
            float2 v = g_sx[i];
            run += (double)expf(v.x);
            if (v.y != 0.0f)
                acc += (double)logf((float)run) - (double)v.x;
        }
    }
    __shared__ double red[T1];
    red[threadIdx.x] = acc;
    __syncthreads();
    for (int off = T1 / 2; off > 0; off >>= 1) {
        if (threadIdx.x < off) red[threadIdx.x] += red[threadIdx.x + off];
        __syncthreads();
    }
    if (threadIdx.x == 0) g_blockAcc[blockIdx.x] = red[0];
}

// --- ordinal loss: O(M) via prefix-sum identity, single block ---
__global__ void ordinal(const float* __restrict__ yp1, const int* __restrict__ Hj,
                        int m, unsigned idx_mask) {
    int t = threadIdx.x;
    int S = (m + 255) / 256;
    long b0 = (long)t * S;
    double tot = 0.0;
    for (int k = 0; k < S; k++) {
        long j = b0 + k;
        if (j < m) {
            int pos = Hj[j];   // position into sorted order (static indices)
            unsigned long long key = g_keys_out[pos];
            unsigned orig = idx_mask - (unsigned)(key & idx_mask);
            float x = yp1[orig];
            g_xh[j] = x;
            tot += exp((double)x);
        }
    }
    __shared__ double sh[256];
    sh[t] = tot;
    __syncthreads();
    for (int off = 1; off < 256; off <<= 1) {
        double v = (t >= off) ? sh[t - off] : 0.0;
        __syncthreads();
        sh[t] += v;
        __syncthreads();
    }
    double run = sh[t] - tot;   // exclusive prefix of exp(xh)
    double acc = 0.0;
    for (int k = 0; k < S; k++) {
        long j = b0 + k;
        if (j < m) {
            double ex = exp((double)g_xh[j]);
            run += ex;                 // inclusive cumsum(exp(xh))[j]
            acc += run / ex;           // exp(-xh_j) * cumsum[j]
        }
    }
    __syncthreads();
    sh[t] = acc;
    __syncthreads();
    for (int off = 128; off > 0; off >>= 1) {
        if (t < off) sh[t] += sh[t + off];
        __syncthreads();
    }
    if (t == 0) {
        double P = 0.5 * (double)m * ((double)m + 1.0);  // pair count (diag contributes 0)
        g_cost2 = P - sh[0];
    }
}

// --- final combine ---
__global__ void final_k(const float* __restrict__ log_vars, float* __restrict__ out,
                        int n, int B) {
    __shared__ double sh[256];
    int t = threadIdx.x;
    double s = 0.0;
    for (int b = t; b < B; b += 256) s += g_blockAcc[b];
    sh[t] = s;
    __syncthreads();
    for (int off = 128; off > 0; off >>= 1) {
        if (t < off) sh[t] += sh[t + off];
        __syncthreads();
    }
    if (t == 0) {
        double lv0 = (double)log_vars[0];
        double lv1 = (double)log_vars[1];
        double prec1 = exp(-lv1);
        if (prec1 > 1.0) prec1 = 1.0;
        if (prec1 < 0.0) prec1 = 0.0;
        double loss = (sh[0] + (double)n * lv0) + (prec1 * g_cost2 + lv1);
        out[0] = (float)loss;
    }
}

extern "C" void kernel_launch(void* const* d_in, const int* in_sizes, int n_in,
                              void* d_out, int out_size) {
    const float* yt0      = (const float*)d_in[0];   // [N,2] (time, event)
    const float* yp0      = (const float*)d_in[2];   // [N,1] xbeta head 0
    const float* yp1      = (const float*)d_in[3];   // [N,1] xbeta head 1
    const int*   Hj       = (const int*)d_in[4];     // [M]
    const float* log_vars = (const float*)d_in[5];   // [2]

    int n = in_sizes[0] / 2;
    int m = in_sizes[4];

    int idx_bits = 0;
    while ((1u << idx_bits) < (unsigned)n) idx_bits++;
    unsigned idx_mask = (1u << idx_bits) - 1u;

    void *p_kin, *p_kout, *p_temp;
    cudaGetSymbolAddress(&p_kin, g_keys_in);
    cudaGetSymbolAddress(&p_kout, g_keys_out);
    cudaGetSymbolAddress(&p_temp, g_cub_temp);

    build_keys<<<(n + 255) / 256, 256>>>(yt0, n, idx_bits, idx_mask);

    size_t tb = 0;
    cub::DeviceRadixSort::SortKeysDescending(
        nullptr, tb, (const unsigned long long*)p_kin,
        (unsigned long long*)p_kout, n, 0, 32 + idx_bits);
    if (tb <= sizeof(g_cub_temp)) {
        cub::DeviceRadixSort::SortKeysDescending(
            p_temp, tb, (const unsigned long long*)p_kin,
            (unsigned long long*)p_kout, n, 0, 32 + idx_bits);
    }

    int B  = (n + PER_BLOCK - 1) / PER_BLOCK;
    int TT = B * T1;

    phase1<<<B, T1>>>(yt0, yp0, n, idx_mask);
    phase2<<<1, 1024>>>(TT);
    phase3<<<B, T1>>>(n);
    ordinal<<<1, 256>>>(yp1, Hj, m, idx_mask);
    final_k<<<1, 256>>>(log_vars, (float*)d_out, n, B);
}

// round 4
// speedup vs baseline: 1.6493x; 1.6493x over previous
#include <cuda_runtime.h>
#include <math.h>

// ---------------------------------------------------------------------------
// loss = sum_i event_i*(log(denom_i) - xbeta0_i) + n*lv0
//      + clip(exp(-lv1),0,1) * cost2 + lv1
// order   = stable descending sort by time (ties: lower original index first)
// denom_i = cumsum(exp(xbeta0[order]))[i]
// cost2   = M(M+1)/2 - sum_ii exp(-xh_ii) * cumsum(exp(xh))[ii],
//           xh = xbeta1[order][Hj]
//
// Sort strategy: time is uniform in [0,1000) -> single-pass value-bucketed
// counting sort (2^18 buckets, avg load 1.0). Buckets are numbered in
// DESCENDING time order (b = NB-1 - value_bucket) so the concatenation of
// buckets is the descending order. Per-bucket insertion-sort fixup on the
// full 50-bit composite key makes the result deterministic & top_k-stable.
// ---------------------------------------------------------------------------

#define MAXN (1 << 19)
#define NB   (1 << 18)          // value buckets
#define MAXM 16384
#define T1 256
#define EPT 8
#define PER_BLOCK (T1 * EPT)    // 2048
#define MAXB (MAXN / PER_BLOCK) // 256
#define NBB  (NB / PER_BLOCK)   // 128 scan blocks over hist

// scratch (allocation-free: __device__ globals)
__device__ unsigned long long g_keys[MAXN];
__device__ int    g_hist[NB];
__device__ int    g_off[NB];
__device__ int    g_off_mut[NB];
__device__ int    g_scanBlk[NBB];
__device__ float2 g_sx[MAXN];       // (xbeta0, event) in sorted order
__device__ double g_coxBlk[MAXB];   // per-block sum of exp(xbeta0)
__device__ double g_blockAcc[MAXB]; // per-block Cox loss
__device__ float  g_xh[MAXM];

__device__ __forceinline__ int bucket_desc(float t) {
    // monotone value->bucket, then flip so bucket 0 = largest times
    int b = (int)(t * ((float)NB / 1000.0f));
    if (b < 0) b = 0;
    if (b > NB - 1) b = NB - 1;
    return (NB - 1) - b;
}

__global__ void zero_hist() {
    int i = blockIdx.x * blockDim.x + threadIdx.x;
    if (i < NB) g_hist[i] = 0;
}

__global__ void hist_k(const float* __restrict__ yt0, int n) {
    int i = blockIdx.x * blockDim.x + threadIdx.x;
    if (i < n) atomicAdd(&g_hist[bucket_desc(yt0[2 * i])], 1);
}

// block partial sums over hist
__global__ void scanA() {
    int b = blockIdx.x, t = threadIdx.x;
    int base = b * PER_BLOCK + t * EPT;
    int s = 0;
#pragma unroll
    for (int e = 0; e < EPT; e++) s += g_hist[base + e];
    __shared__ int sh[T1];
    sh[t] = s;
    __syncthreads();
    for (int off = T1 / 2; off > 0; off >>= 1) {
        if (t < off) sh[t] += sh[t + off];
        __syncthreads();
    }
    if (t == 0) g_scanBlk[b] = sh[0];
}

// exclusive scan over hist -> off (and off_mut copy)
__global__ void scanB() {
    int b = blockIdx.x, t = threadIdx.x;
    __shared__ int shb[T1];
    int v = 0;
    for (int k = t; k < b; k += T1) v += g_scanBlk[k];
    shb[t] = v;
    __syncthreads();
    for (int off = T1 / 2; off > 0; off >>= 1) {
        if (t < off) shb[t] += shb[t + off];
        __syncthreads();
    }
    int base_val = shb[0];

    int base_i = b * PER_BLOCK + t * EPT;
    int loc[EPT];
    int s = 0;
#pragma unroll
    for (int e = 0; e < EPT; e++) { loc[e] = g_hist[base_i + e]; s += loc[e]; }

    __shared__ int sh[T1];
    sh[t] = s;
    __syncthreads();
    for (int off = 1; off < T1; off <<= 1) {
        int u = (t >= off) ? sh[t - off] : 0;
        __syncthreads();
        sh[t] += u;
        __syncthreads();
    }
    int run = base_val + sh[t] - s;   // exclusive prefix for this thread
#pragma unroll
    for (int e = 0; e < EPT; e++) {
        g_off[base_i + e] = run;
        g_off_mut[base_i + e] = run;
        run += loc[e];
    }
}

// place composite keys into bucket slots (intra-bucket order arbitrary here)
__global__ void scatter_k(const float* __restrict__ yt0, int n, int idx_bits,
                          unsigned idx_mask) {
    int i = blockIdx.x * blockDim.x + threadIdx.x;
    if (i >= n) return;
    float t = yt0[2 * i];
    unsigned u = __float_as_uint(t);
    u = (u & 0x80000000u) ? ~u : (u | 0x80000000u);   // total order on floats
    unsigned long long key = ((unsigned long long)u << idx_bits) |
                             (unsigned long long)(idx_mask - (unsigned)i);
    int b = bucket_desc(t);
    int pos = atomicAdd(&g_off_mut[b], 1);
    g_keys[pos] = key;
}

// per-bucket insertion sort (descending by composite key):
// larger time first; within ties, larger (idx_mask - i) first = smaller i first
__global__ void fixup_k() {
    int b = blockIdx.x * blockDim.x + threadIdx.x;
    if (b >= NB) return;
    int s = g_off[b], e = g_off_mut[b];
    for (int i = s + 1; i < e; i++) {
        unsigned long long k = g_keys[i];
        int j = i - 1;
        while (j >= s && g_keys[j] < k) { g_keys[j + 1] = g_keys[j]; j--; }
        g_keys[j + 1] = k;
    }
}

// gather payload in sorted order; per-block exp sums
__global__ void cox1(const float* __restrict__ yt0, const float* __restrict__ yp0,
                     int n, unsigned idx_mask) {
    int t = threadIdx.x;
    long base = (long)(blockIdx.x * PER_BLOCK) + (long)t * EPT;
    double s = 0.0;
#pragma unroll
    for (int e = 0; e < EPT; e++) {
        long i = base + e;
        if (i < n) {
            unsigned long long k = g_keys[i];
            unsigned orig = idx_mask - (unsigned)(k & idx_mask);
            float xb = yp0[orig];
            float ev = yt0[2 * orig + 1];
            g_sx[i] = make_float2(xb, ev);
            s += (double)expf(xb);
        }
    }
    __shared__ double sh[T1];
    sh[t] = s;
    __syncthreads();
    for (int off = T1 / 2; off > 0; off >>= 1) {
        if (t < off) sh[t] += sh[t + off];
        __syncthreads();
    }
    if (t == 0) g_coxBlk[blockIdx.x] = sh[0];
}

// per-block base (sum of predecessor block sums) + local prefix + loss
__global__ void cox2(int n) {
    int b = blockIdx.x, t = threadIdx.x;
    __shared__ double shb[T1];
    double v = 0.0;
    for (int k = t; k < b; k += T1) v += g_coxBlk[k];
    shb[t] = v;
    __syncthreads();
    for (int off = T1 / 2; off > 0; off >>= 1) {
        if (t < off) shb[t] += shb[t + off];
        __syncthreads();
    }
    double base_val = shb[0];

    long base_i = (long)(b * PER_BLOCK) + (long)t * EPT;
    double ex[EPT];
    double s = 0.0;
#pragma unroll
    for (int e = 0; e < EPT; e++) {
        long i = base_i + e;
        ex[e] = (i < n) ? (double)expf(g_sx[i].x) : 0.0;
        s += ex[e];
    }
    __shared__ double sh[T1];
    sh[t] = s;
    __syncthreads();
    for (int off = 1; off < T1; off <<= 1) {
        double u = (t >= off) ? sh[t - off] : 0.0;
        __syncthreads();
        sh[t] += u;
        __syncthreads();
    }
    double run = base_val + sh[t] - s;   // exclusive prefix for this thread
    double acc = 0.0;
#pragma unroll
    for (int e = 0; e < EPT; e++) {
        long i = base_i + e;
        if (i < n) {
            run += ex[e];
            float2 vv = g_sx[i];
            if (vv.y != 0.0f)
                acc += (double)logf((float)run) - (double)vv.x;
        }
    }
    __syncthreads();
    sh[t] = acc;
    __syncthreads();
    for (int off = T1 / 2; off > 0; off >>= 1) {
        if (t < off) sh[t] += sh[t + off];
        __syncthreads();
    }
    if (t == 0) g_blockAcc[b] = sh[0];
}

// ordinal loss (O(M) via prefix identity) + final combine, single block
__global__ void ordinal_final(const float* __restrict__ yp1,
                              const int* __restrict__ Hj,
                              const float* __restrict__ log_vars,
                              float* __restrict__ out,
                              int n, int m, unsigned idx_mask, int Bc) {
    int t = threadIdx.x;
    int S = (m + 255) / 256;
    long b0 = (long)t * S;
    double tot = 0.0;
    for (int k = 0; k < S; k++) {
        long j = b0 + k;
        if (j < m) {
            int pos = Hj[j];                    // rank into sorted order
            unsigned long long key = g_keys[pos];
            unsigned orig = idx_mask - (unsigned)(key & idx_mask);
            float x = yp1[orig];
            g_xh[j] = x;
            tot += exp((double)x);
        }
    }
    __shared__ double sh[256];
    sh[t] = tot;
    __syncthreads();
    for (int off = 1; off < 256; off <<= 1) {
        double v = (t >= off) ? sh[t - off] : 0.0;
        __syncthreads();
        sh[t] += v;
        __syncthreads();
    }
    double run = sh[t] - tot;   // exclusive prefix of exp(xh)
    double acc = 0.0;
    for (int k = 0; k < S; k++) {
        long j = b0 + k;
        if (j < m) {
            double exv = exp((double)g_xh[j]);
            run += exv;                 // inclusive cumsum(exp(xh))[j]
            acc += run / exv;           // exp(-xh_j) * cumsum[j]
        }
    }
    __syncthreads();
    sh[t] = acc;
    __syncthreads();
    for (int off = 128; off > 0; off >>= 1) {
        if (t < off) sh[t] += sh[t + off];
        __syncthreads();
    }
    double cost2 = 0.5 * (double)m * ((double)m + 1.0) - sh[0];
    __syncthreads();

    // sum Cox block losses
    double s2 = 0.0;
    for (int b = t; b < Bc; b += 256) s2 += g_blockAcc[b];
    sh[t] = s2;
    __syncthreads();
    for (int off = 128; off > 0; off >>= 1) {
        if (t < off) sh[t] += sh[t + off];
        __syncthreads();
    }
    if (t == 0) {
        double lv0 = (double)log_vars[0];
        double lv1 = (double)log_vars[1];
        double prec1 = exp(-lv1);
        if (prec1 > 1.0) prec1 = 1.0;
        if (prec1 < 0.0) prec1 = 0.0;
        double loss = (sh[0] + (double)n * lv0) + (prec1 * cost2 + lv1);
        out[0] = (float)loss;
    }
}

extern "C" void kernel_launch(void* const* d_in, const int* in_sizes, int n_in,
                              void* d_out, int out_size) {
    const float* yt0      = (const float*)d_in[0];   // [N,2] (time, event)
    const float* yp0      = (const float*)d_in[2];   // [N,1] xbeta head 0
    const float* yp1      = (const float*)d_in[3];   // [N,1] xbeta head 1
    const int*   Hj       = (const int*)d_in[4];     // [M]
    const float* log_vars = (const float*)d_in[5];   // [2]

    int n = in_sizes[0] / 2;
    int m = in_sizes[4];

    int idx_bits = 0;
    while ((1u << idx_bits) < (unsigned)n) idx_bits++;
    unsigned idx_mask = (1u << idx_bits) - 1u;

    int gN = (n + 255) / 256;
    int Bc = (n + PER_BLOCK - 1) / PER_BLOCK;

    zero_hist<<<NB / 256, 256>>>();
    hist_k<<<gN, 256>>>(yt0, n);
    scanA<<<NBB, T1>>>();
    scanB<<<NBB, T1>>>();
    scatter_k<<<gN, 256>>>(yt0, n, idx_bits, idx_mask);
    fixup_k<<<NB / 256, 256>>>();
    cox1<<<Bc, T1>>>(yt0, yp0, n, idx_mask);
    cox2<<<Bc, T1>>>(n);
    ordinal_final<<<1, 256>>>(yp1, Hj, log_vars, (float*)d_out, n, m, idx_mask, Bc);
}